// round 16
// baseline (speedup 1.0000x reference)
#include <cuda_runtime.h>
#include <math_constants.h>
#include <cstdint>

#define BB 8192
#define CC 2048
#define NBINS 4096
#define GAMA 0.3f
#define FULLM 0xffffffffu
#define ROWS_PER_BLK 4
#define TILE_BYTES (ROWS_PER_BLK * CC * 4)   // 32768

// ---------------- scratch (static __device__, no allocs) ----------------
__device__ float g_rowmax[BB]; // max over cols [1,C)
__device__ float g_neg[BB];    // sigmoid(max excluding label col and col 0)
__device__ float g_posm[BB];   // m_i = sigmoid(x[i,y])-gamma, +INF invalid
__device__ int   g_notI64;     // 1 = labels int32, 0 = int64

__device__ __forceinline__ float sigmoidf_(float v) { return 1.0f / (1.0f + __expf(-v)); }
// Monotonic bin for v in (0,1): positive-float bits are order-preserving.
__device__ __forceinline__ int binOf(float v) { return (int)(__float_as_uint(v) >> 19); }

__device__ __forceinline__ float max4(float4 v) {
    return fmaxf(fmaxf(v.x, v.y), fmaxf(v.z, v.w));
}
__device__ __forceinline__ uint32_t smem_u32(const void* p) {
    uint32_t a;
    asm("{ .reg .u64 t; cvta.to.shared.u64 t, %1; cvt.u32.u64 %0, t; }" : "=r"(a) : "l"(p));
    return a;
}

// ---------------- K1: 4 rows per block via ONE 32KB TMA bulk copy ----------------
__global__ __launch_bounds__(128) void k_row(const float* __restrict__ x,
                                             const int* __restrict__ wy) {
    const int tid  = threadIdx.x;
    const int lane = tid & 31;
    const int w    = tid >> 5;

    if (blockIdx.x == BB / ROWS_PER_BLK) {
        // dedicated dtype-detect block: reads only words [0, BB) — safe for both dtypes.
        // int64 labels (<2048) -> odd words are zero high halves.
        int f = 0;
        for (int i = tid; i < BB / 2; i += 128) f |= wy[2 * i + 1];
#pragma unroll
        for (int o = 16; o; o >>= 1) f |= __shfl_xor_sync(FULLM, f, o);
        __shared__ int sf[4];
        if (lane == 0) sf[w] = f;
        __syncthreads();
        if (tid == 0) g_notI64 = ((sf[0] | sf[1] | sf[2] | sf[3]) != 0);
        return;
    }

    __shared__ __align__(128) float tile[ROWS_PER_BLK * CC];
    __shared__ __align__(8) unsigned long long mbar;

    const uint32_t mb = smem_u32(&mbar);
    const uint32_t ts = smem_u32(tile);

    if (tid == 0)
        asm volatile("mbarrier.init.shared.b64 [%0], 1;" :: "r"(mb) : "memory");
    __syncthreads();

    if (tid == 0) {
        asm volatile("mbarrier.arrive.expect_tx.shared.b64 _, [%0], %1;"
                     :: "r"(mb), "r"((uint32_t)TILE_BYTES) : "memory");
        const void* src = x + (size_t)blockIdx.x * ROWS_PER_BLK * CC;
        asm volatile(
            "cp.async.bulk.shared::cta.global.mbarrier::complete_tx::bytes [%0], [%1], %2, [%3];"
            :: "r"(ts), "l"(src), "r"((uint32_t)TILE_BYTES), "r"(mb) : "memory");
    }

    // wait (acquire) for TMA completion, parity 0
    {
        uint32_t done;
        asm volatile(
            "{\n\t.reg .pred p;\n\t"
            "mbarrier.try_wait.parity.acquire.cta.shared::cta.b64 p, [%1], 0;\n\t"
            "selp.b32 %0, 1, 0, p;\n\t}"
            : "=r"(done) : "r"(mb) : "memory");
        if (!done) {
            asm volatile(
                "{\n\t.reg .pred P1;\n\t"
                "W_%=:\n\t"
                "mbarrier.try_wait.parity.acquire.cta.shared::cta.b64 P1, [%0], 0, 0x989680;\n\t"
                "@P1 bra.uni D_%=;\n\t"
                "bra.uni W_%=;\n\t"
                "D_%=:\n\t}"
                :: "r"(mb) : "memory");
        }
    }

    // reduce 4 rows from smem (conflict-free LDS.128)
    float m0 = -CUDART_INF_F, m1 = -CUDART_INF_F, m2 = -CUDART_INF_F, m3 = -CUDART_INF_F;
#pragma unroll
    for (int k = 0; k < 4; k++) {
        int c4 = tid + 128 * k;
        float4 v0 = *(const float4*)&tile[0 * CC + c4 * 4];
        float4 v1 = *(const float4*)&tile[1 * CC + c4 * 4];
        float4 v2 = *(const float4*)&tile[2 * CC + c4 * 4];
        float4 v3 = *(const float4*)&tile[3 * CC + c4 * 4];
        if (k == 0 && tid == 0) {   // exclude global col 0 of each row
            v0.x = -CUDART_INF_F; v1.x = -CUDART_INF_F;
            v2.x = -CUDART_INF_F; v3.x = -CUDART_INF_F;
        }
        m0 = fmaxf(m0, max4(v0));
        m1 = fmaxf(m1, max4(v1));
        m2 = fmaxf(m2, max4(v2));
        m3 = fmaxf(m3, max4(v3));
    }
#pragma unroll
    for (int o = 16; o; o >>= 1) {
        m0 = fmaxf(m0, __shfl_xor_sync(FULLM, m0, o));
        m1 = fmaxf(m1, __shfl_xor_sync(FULLM, m1, o));
        m2 = fmaxf(m2, __shfl_xor_sync(FULLM, m2, o));
        m3 = fmaxf(m3, __shfl_xor_sync(FULLM, m3, o));
    }
    __shared__ float wr[4][4];          // [warp][row]
    if (lane == 0) { wr[w][0] = m0; wr[w][1] = m1; wr[w][2] = m2; wr[w][3] = m3; }
    __syncthreads();
    if (tid == 0) {
        float4 r;
        r.x = fmaxf(fmaxf(wr[0][0], wr[1][0]), fmaxf(wr[2][0], wr[3][0]));
        r.y = fmaxf(fmaxf(wr[0][1], wr[1][1]), fmaxf(wr[2][1], wr[3][1]));
        r.z = fmaxf(fmaxf(wr[0][2], wr[1][2]), fmaxf(wr[2][2], wr[3][2]));
        r.w = fmaxf(fmaxf(wr[0][3], wr[1][3]), fmaxf(wr[2][3], wr[3][3]));
        *(float4*)&g_rowmax[blockIdx.x * ROWS_PER_BLK] = r;   // 16B aligned
    }
}

// ---------------- K1b: label select + pos gather; rare cooperative rescan ----------------
__global__ __launch_bounds__(128) void k_pos(const float* __restrict__ x,
                                             const int* __restrict__ wy) {
    const int i    = blockIdx.x * 128 + threadIdx.x;   // 64*128 = 8192
    const int lane = threadIdx.x & 31;
    const int notI64 = g_notI64;
    // wy[2*i] only dereferenced when labels proven int64 (buffer has 2*BB words)
    int yq = notI64 ? wy[i] : wy[2 * i];
    float m1 = g_rowmax[i];
    float px = __ldg(&x[(size_t)i * CC + yq]);

    float neg = m1;                       // correct unless label col holds the max
    bool need = (yq != 0) && (px == m1);  // exact: px is an element, m1 the exact max
    unsigned bal = __ballot_sync(FULLM, need);
    while (bal) {                         // ~4 rows expected across the whole grid
        int l  = __ffs(bal) - 1; bal &= bal - 1;
        int ri = __shfl_sync(FULLM, i,  l);
        int ry = __shfl_sync(FULLM, yq, l);
        const float4* xr = (const float4*)(x + (size_t)ri * CC);
        float mm = -CUDART_INF_F;
        for (int c4 = lane; c4 < CC / 4; c4 += 32) {
            float4 v = __ldg(xr + c4);
            int c = c4 * 4;
            if (c == 0)      v.x = -CUDART_INF_F;
            if (c + 0 == ry) v.x = -CUDART_INF_F;
            if (c + 1 == ry) v.y = -CUDART_INF_F;
            if (c + 2 == ry) v.z = -CUDART_INF_F;
            if (c + 3 == ry) v.w = -CUDART_INF_F;
            mm = fmaxf(mm, max4(v));
        }
#pragma unroll
        for (int o = 16; o; o >>= 1) mm = fmaxf(mm, __shfl_xor_sync(FULLM, mm, o));
        if (lane == l) neg = mm;          // exact masked max for this row
    }
    g_neg[i]  = sigmoidf_(neg);
    g_posm[i] = (yq != 0) ? (sigmoidf_(px) - GAMA) : CUDART_INF_F;
}

// ---------------- K2: hist + scan + scatter + suffix + queries (all smem, warp scans) ----------------
// smem layout (bytes from base):
//   [0      , 65544 )  double sS1[8193]   (overlay: float sraw[8192] @0,
//   [65544  , 131088)  double sS2[8193]    int shist[4096] @32768, int scursor[4096] @49152)
//   [131088 , 163856)  float  ssorted[8192]
//   [163856 , 180248)  int    sbinStart[4097] (+pad)
//   [180248 , 188440)  double p1[1024]
//   [188440 , 196632)  double p2[1024]
//   [196632 , 200728)  int    iscan[1024]
#define K2_SMEM 200728

__global__ __launch_bounds__(1024, 1) void k_main(float* __restrict__ out) {
    extern __shared__ unsigned char sm[];
    double* sS1      = (double*)(sm);
    double* sS2      = (double*)(sm + 65544);
    float*  ssorted  = (float*) (sm + 131088);
    int*    sbinStart= (int*)   (sm + 163856);
    double* p1       = (double*)(sm + 180248);
    double* p2       = (double*)(sm + 188440);
    int*    iscan    = (int*)   (sm + 196632);
    float*  sraw     = (float*) (sm);           // overlay, dead before sS1 written
    int*    shist    = (int*)   (sm + 32768);   // overlay
    int*    scursor  = (int*)   (sm + 49152);   // overlay

    const int tid  = threadIdx.x;
    const int lane = tid & 31;
    const int wid  = tid >> 5;

    // ---- phase 1: contiguous loads; neg -> smem, m -> regs ----
    float pm[8];
#pragma unroll
    for (int k = 0; k < 8; k++) {
        int i = tid + k * 1024;
        sraw[i] = g_neg[i];
        pm[k]   = g_posm[i];
    }
    for (int i = tid; i < NBINS; i += 1024) shist[i] = 0;
    __syncthreads();

    // ---- phase 2: histogram (warp-aggregated atomics) ----
#pragma unroll
    for (int k = 0; k < 8; k++) {
        int b = binOf(sraw[tid + k * 1024]);
        unsigned mask = __match_any_sync(FULLM, b);
        if (lane == (__ffs(mask) - 1)) atomicAdd(&shist[b], __popc(mask));
    }
    __syncthreads();

    // ---- phase 3: exclusive scan over 4096 bins (warp-shuffle scan) ----
    const int tb = tid * 4;
    int h0 = shist[tb], h1 = shist[tb + 1], h2 = shist[tb + 2], h3 = shist[tb + 3];
    int tsum = h0 + h1 + h2 + h3;
    int v = tsum;
#pragma unroll
    for (int o = 1; o < 32; o <<= 1) {
        int t = __shfl_up_sync(FULLM, v, o);
        if (lane >= o) v += t;
    }
    if (lane == 31) iscan[wid] = v;             // warp totals
    __syncthreads();
    if (wid == 0) {
        int w = iscan[lane];
        int s = w;
#pragma unroll
        for (int o = 1; o < 32; o <<= 1) {
            int t = __shfl_up_sync(FULLM, s, o);
            if (lane >= o) s += t;
        }
        iscan[32 + lane] = s - w;               // exclusive warp offsets
    }
    __syncthreads();
    {
        int ex = v + iscan[32 + wid] - tsum;    // exclusive prefix for this thread
        sbinStart[tb] = ex;     scursor[tb]     = ex; ex += h0;
        sbinStart[tb + 1] = ex; scursor[tb + 1] = ex; ex += h1;
        sbinStart[tb + 2] = ex; scursor[tb + 2] = ex; ex += h2;
        sbinStart[tb + 3] = ex; scursor[tb + 3] = ex; ex += h3;
        if (tid == 1023) sbinStart[NBINS] = ex; // = BB
    }
    __syncthreads();

    // ---- phase 4: scatter into bin-grouped order (warp-aggregated) ----
#pragma unroll
    for (int k = 0; k < 8; k++) {
        float val = sraw[tid + k * 1024];
        int b = binOf(val);
        unsigned mask = __match_any_sync(FULLM, b);
        int leader = __ffs(mask) - 1;
        int pos0 = 0;
        if (lane == leader) pos0 = atomicAdd(&scursor[b], __popc(mask));
        pos0 = __shfl_sync(FULLM, pos0, leader);
        ssorted[pos0 + __popc(mask & ((1u << lane) - 1u))] = val;
    }
    __syncthreads();   // sraw/shist/scursor dead from here

    // ---- phase 5: element-level suffix sums (double), warp-shuffle suffix scan ----
    const int base8 = tid * 8;
    double tl1[8], tl2[8];
    double a1 = 0.0, a2 = 0.0;
#pragma unroll
    for (int k = 7; k >= 0; --k) {
        float n = ssorted[base8 + k];
        a1 += (double)n;
        a2 += (double)n * (double)n;
        tl1[k] = a1; tl2[k] = a2;
    }
    double s1 = a1, s2 = a2;
#pragma unroll
    for (int o = 1; o < 32; o <<= 1) {
        double t1 = __shfl_down_sync(FULLM, s1, o);
        double t2 = __shfl_down_sync(FULLM, s2, o);
        if (lane + o < 32) { s1 += t1; s2 += t2; }
    }
    if (lane == 0) { p1[wid] = s1; p2[wid] = s2; }  // warp totals
    __syncthreads();
    if (wid == 0) {
        double w1 = p1[lane], w2 = p2[lane];
        double e1 = w1, e2 = w2;
#pragma unroll
        for (int o = 1; o < 32; o <<= 1) {
            double t1 = __shfl_down_sync(FULLM, e1, o);
            double t2 = __shfl_down_sync(FULLM, e2, o);
            if (lane + o < 32) { e1 += t1; e2 += t2; }
        }
        p1[32 + lane] = e1 - w1;               // exclusive suffix of higher warps
        p2[32 + lane] = e2 - w2;
    }
    __syncthreads();
    {
        double o1 = s1 + p1[32 + wid] - a1;    // sum strictly after this thread's chunk
        double o2 = s2 + p2[32 + wid] - a2;
#pragma unroll
        for (int k = 0; k < 8; k++) {
            sS1[base8 + k] = tl1[k] + o1;
            sS2[base8 + k] = tl2[k] + o2;
        }
        if (tid == 0) { sS1[BB] = 0.0; sS2[BB] = 0.0; }
    }
    __syncthreads();

    // ---- phase 6: queries + warp reduction ----
    double acc = 0.0;
    int vc = 0;
#pragma unroll
    for (int k = 0; k < 8; k++) {
        float m = pm[k];
        if (!(m < 1.0f)) continue;       // invalid (+INF)
        vc++;
        long long cnt; double S1, S2;
        if (m <= 0.0f) {
            cnt = BB; S1 = sS1[0]; S2 = sS2[0];
        } else {
            int b = binOf(m); if (b > NBINS - 1) b = NBINS - 1;
            int st = sbinStart[b], en = sbinStart[b + 1];
            cnt = BB - en; S1 = sS1[en]; S2 = sS2[en];
            for (int t = st; t < en; t++) {          // exact boundary-bin scan
                float n = ssorted[t];
                if (n > m) { cnt++; S1 += (double)n; S2 += (double)n * (double)n; }
            }
        }
        double md = (double)m;
        acc += (double)cnt * md * md - 2.0 * md * S1 + S2;
    }
#pragma unroll
    for (int o = 16; o; o >>= 1) {
        acc += __shfl_down_sync(FULLM, acc, o);
        vc  += __shfl_down_sync(FULLM, vc,  o);
    }
    if (lane == 0) { p1[wid] = acc; iscan[wid] = vc; }
    __syncthreads();
    if (tid == 0) {
        double s = 0.0; int c = 0;
#pragma unroll
        for (int w = 0; w < 32; w++) { s += p1[w]; c += iscan[w]; }
        out[0] = (float)(s / ((double)c + 1.0) / ((double)BB + 1.0));
    }
}

// ---------------- launch ----------------
extern "C" void kernel_launch(void* const* d_in, const int* in_sizes, int n_in,
                              void* d_out, int out_size) {
    const float* x = (const float*)d_in[0];
    const int*   y = (const int*)d_in[1];

    k_row<<<BB / ROWS_PER_BLK + 1, 128>>>(x, y);
    k_pos<<<64, 128>>>(x, y);
    cudaFuncSetAttribute(k_main, cudaFuncAttributeMaxDynamicSharedMemorySize, K2_SMEM);
    k_main<<<1, 1024, K2_SMEM>>>((float*)d_out);
}